// round 11
// baseline (speedup 1.0000x reference)
#include <cuda_runtime.h>
#include <cuda_bf16.h>
#include <cstdint>

// Inputs: 0 positions f32 (N)*3 | 1 cell f32 9 | 2 cutoffs f32 2
//         3 shifts i32 S*3 | 4 ml_idx i32 | 5 mm_idx i32
// Output (f32 flat): [0,2P) idx_i | [2P,4P) idx_j | [4P,10P) offsets(2P x 3)
//                    [10P,12P) d2_full | [12P,16P) masks(2 x 2P)
// P=(S+1)*n_ml*n_mm.  idx_i=[pi,pj], idx_j=[pj,pi], offsets=[-sv,+sv], d2=[d2,d2].
//
// R11 = R10 partition + full strength reduction:
//  - pair loop: 6 running float4 pointers (stride P0/4), no 64-bit rebuilds
//  - fill loops: running pointer += 256; "full" blocks drop bounds predicate
//  (a) pair-compute blocks: d2 + masks only
//  (b) idx-fill blocks: [0,4P), contiguous 16KB runs
//  (c) offsets-fill blocks: [4P,10P), contiguous 16KB runs

__device__ __forceinline__ void load_cell(const float* __restrict__ cell,
                                          float c[9]) {
    #pragma unroll
    for (int u = 0; u < 9; u++) c[u] = __ldg(cell + u);
}

__device__ __forceinline__ void shift_vec(const int* __restrict__ shifts, int s,
                                          const float c[9],
                                          float& svx, float& svy, float& svz) {
    float sf0 = 0.f, sf1 = 0.f, sf2 = 0.f;
    if (s > 0) {
        sf0 = (float)__ldg(shifts + (s - 1) * 3 + 0);
        sf1 = (float)__ldg(shifts + (s - 1) * 3 + 1);
        sf2 = (float)__ldg(shifts + (s - 1) * 3 + 2);
    }
    svx = sf0 * c[0] + sf1 * c[3] + sf2 * c[6];
    svy = sf0 * c[1] + sf1 * c[4] + sf2 * c[7];
    svz = sf0 * c[2] + sf1 * c[5] + sf2 * c[8];
}

// offsets fill: 4096 consecutive float4s per block
__device__ __forceinline__ void offsets_fill(const int* __restrict__ shifts,
                                             const float c[9],
                                             float* __restrict__ out,
                                             long long fb, long long P,
                                             long long P0, int off_aligned)
{
    const long long tot4 = (6 * P) >> 2;
    const long long base4 = fb * 4096;
    if (base4 >= tot4) return;
    float4* dst = reinterpret_cast<float4*>(out + 4 * P);
    const long long halfF = 3 * P;

    if (off_aligned) {
        const long long fbase = base4 * 4;
        const bool negh = fbase < halfF;
        const long long fl = negh ? fbase : fbase - halfF;
        const int s = (int)(fl / (3 * P0));
        float svx, svy, svz;
        shift_vec(shifts, s, c, svx, svy, svz);
        const float X = negh ? -svx : svx;
        const float Y = negh ? -svy : svy;
        const float Z = negh ? -svz : svz;
        const float4 var[3] = { make_float4(X, Y, Z, X),
                                make_float4(Y, Z, X, Y),
                                make_float4(Z, X, Y, Z) };
        float4* p = dst + base4 + threadIdx.x;
        int v = (int)((base4 + threadIdx.x) % 3);
        const bool full = (base4 + 4096 <= tot4);
        if (full) {
            #pragma unroll
            for (int u = 0; u < 16; u++) {
                *p = var[v];
                p += 256;                       // +256 ≡ +1 (mod 3)
                v++; if (v == 3) v = 0;
            }
        } else {
            long long f4 = base4 + threadIdx.x;
            #pragma unroll
            for (int u = 0; u < 16; u++) {
                if (f4 < tot4) *p = var[v];
                p += 256; f4 += 256;
                v++; if (v == 3) v = 0;
            }
        }
    } else {
        for (int u = 0; u < 16; u++) {
            long long f4 = base4 + threadIdx.x + (long long)u * 256;
            if (f4 >= tot4) break;
            #pragma unroll
            for (int w = 0; w < 4; w++) {
                long long f = f4 * 4 + w;
                const bool negh = f < halfF;
                const long long fl = negh ? f : f - halfF;
                const long long row = fl / 3;
                const int comp = (int)(fl - row * 3);
                const int s = (int)(row / P0);
                float svx, svy, svz;
                shift_vec(shifts, s, c, svx, svy, svz);
                float val = (comp == 0) ? svx : (comp == 1) ? svy : svz;
                if (negh) val = -val;
                out[4 * P + f] = val;
            }
        }
    }
}

// idx fill: region [0,4P). Quarters: 0=pi, 1=pj, 2=pj, 3=pi.
// Host-gated: P%16384==0, P0%16384==0 -> every block full, inside one
// quarter and one P0 tile. Inner loop: store, ptr+=256, j wrap. One div.
__device__ __forceinline__ void idx_fill(const int* __restrict__ ml_idx,
                                         const int* __restrict__ mm_idx,
                                         float* __restrict__ out,
                                         long long fb, long long P,
                                         long long P0, int n_mm)
{
    const long long tot4 = P;              // float4s in [0,4P)
    const long long q4   = P >> 2;         // float4s per quarter
    const long long base4 = fb * 4096;
    if (base4 >= tot4) return;

    const int q = (int)(base4 / q4);
    const long long rem4 = base4 - (long long)q * q4;
    const int local4 = (int)(rem4 % (P0 >> 2));
    int f = (local4 + (int)threadIdx.x) * 4;
    const bool is_pi = (q == 0 || q == 3);

    int i = f / n_mm;
    int j = f - i * n_mm;

    float4* p = reinterpret_cast<float4*>(out) + base4 + threadIdx.x;
    if (is_pi) {
        #pragma unroll
        for (int u = 0; u < 16; u++) {
            const float fi = (float)__ldg(ml_idx + i);
            *p = make_float4(fi, fi, fi, fi);
            p += 256;
            j += 1024;
            if (j >= n_mm) { j -= n_mm; i++; }
        }
    } else {
        #pragma unroll
        for (int u = 0; u < 16; u++) {
            const int4 jv = __ldg(reinterpret_cast<const int4*>(mm_idx + j));
            *p = make_float4((float)jv.x, (float)jv.y, (float)jv.z, (float)jv.w);
            p += 256;
            j += 1024;
            if (j >= n_mm) { j -= n_mm; i++; }
        }
    }
}

// ─────────── fast kernel: pair-compute (d2+masks) + both fills ───────────────
__global__ __launch_bounds__(256)
void nbrlist_sloop(const float* __restrict__ pos,
                   const float* __restrict__ cell,
                   const float* __restrict__ cutoffs,
                   const int*   __restrict__ shifts,
                   const int*   __restrict__ ml_idx,
                   const int*   __restrict__ mm_idx,
                   float* __restrict__ out,
                   int n_ml, int n_mm, int S_img, long long P,
                   long long pairBlocks, long long idxBlocks,
                   int jchunks, int off_aligned)
{
    const long long P0 = (long long)n_ml * n_mm;

    if (blockIdx.x >= (unsigned)(pairBlocks + idxBlocks)) {
        float c[9];
        load_cell(cell, c);
        offsets_fill(shifts, c, out,
                     (long long)blockIdx.x - pairBlocks - idxBlocks,
                     P, P0, off_aligned);
        return;
    }
    if (blockIdx.x >= (unsigned)pairBlocks) {
        idx_fill(ml_idx, mm_idx, out, (long long)blockIdx.x - pairBlocks,
                 P, P0, n_mm);
        return;
    }

    float c[9];
    load_cell(cell, c);

    const int bi = (int)blockIdx.x;
    const int i  = bi / jchunks;
    const int jc = bi - i * jchunks;
    const int j0 = jc * 1024 + (int)threadIdx.x * 4;

    const float cut0 = __ldg(cutoffs + 0), cut1 = __ldg(cutoffs + 1);
    const float c0sq = cut0 * cut0, c1sq = cut1 * cut1;

    const int ia = __ldg(ml_idx + i);
    const float pix0 = __ldg(pos + 3 * ia + 0);
    const float piy0 = __ldg(pos + 3 * ia + 1);
    const float piz0 = __ldg(pos + 3 * ia + 2);

    const int4 jv = __ldg(reinterpret_cast<const int4*>(mm_idx + j0));
    float pjx[4], pjy[4], pjz[4];

    const bool contig = (jv.w == jv.x + 3) && (((3 * jv.x) & 3) == 0);
    if (contig) {
        const float4* pb = reinterpret_cast<const float4*>(pos + 3 * jv.x);
        const float4 v0 = __ldg(pb + 0);
        const float4 v1 = __ldg(pb + 1);
        const float4 v2 = __ldg(pb + 2);
        pjx[0] = v0.x; pjy[0] = v0.y; pjz[0] = v0.z;
        pjx[1] = v0.w; pjy[1] = v1.x; pjz[1] = v1.y;
        pjx[2] = v1.z; pjy[2] = v1.w; pjz[2] = v2.x;
        pjx[3] = v2.y; pjy[3] = v2.z; pjz[3] = v2.w;
    } else {
        const int jidx[4] = {jv.x, jv.y, jv.z, jv.w};
        #pragma unroll
        for (int u = 0; u < 4; u++) {
            pjx[u] = __ldg(pos + 3 * jidx[u] + 0);
            pjy[u] = __ldg(pos + 3 * jidx[u] + 1);
            pjz[u] = __ldg(pos + 3 * jidx[u] + 2);
        }
    }

    const long long prow = (long long)i * n_mm + j0;
    const long long step4 = P0 >> 2;           // float4 stride per image

    // running pointers for the 6 streams
    float4* q_d2a = reinterpret_cast<float4*>(out + 10 * P + prow);
    float4* q_d2b = reinterpret_cast<float4*>(out + 11 * P + prow);
    float4* q_m0a = reinterpret_cast<float4*>(out + 12 * P + prow);
    float4* q_m0b = reinterpret_cast<float4*>(out + 13 * P + prow);
    float4* q_m1a = reinterpret_cast<float4*>(out + 14 * P + prow);
    float4* q_m1b = reinterpret_cast<float4*>(out + 15 * P + prow);

    for (int s = 0; s < S_img; s++) {
        float svx, svy, svz;
        shift_vec(shifts, s, c, svx, svy, svz);
        const float pix = pix0 + svx;
        const float piy = piy0 + svy;
        const float piz = piz0 + svz;

        float d2v[4];
        #pragma unroll
        for (int u = 0; u < 4; u++) {
            const float dx = pix - pjx[u];
            const float dy = piy - pjy[u];
            const float dz = piz - pjz[u];
            d2v[u] = dx * dx + dy * dy + dz * dz;
        }

        const float4 v_d2 = make_float4(d2v[0], d2v[1], d2v[2], d2v[3]);
        const float4 m0 = make_float4(d2v[0] < c0sq ? 1.f : 0.f,
                                      d2v[1] < c0sq ? 1.f : 0.f,
                                      d2v[2] < c0sq ? 1.f : 0.f,
                                      d2v[3] < c0sq ? 1.f : 0.f);
        const float4 m1 = make_float4(d2v[0] < c1sq ? 1.f : 0.f,
                                      d2v[1] < c1sq ? 1.f : 0.f,
                                      d2v[2] < c1sq ? 1.f : 0.f,
                                      d2v[3] < c1sq ? 1.f : 0.f);

        *q_d2a = v_d2;  q_d2a += step4;
        *q_d2b = v_d2;  q_d2b += step4;
        *q_m0a = m0;    q_m0a += step4;
        *q_m0b = m0;    q_m0b += step4;
        *q_m1a = m1;    q_m1a += step4;
        *q_m1b = m1;    q_m1b += step4;
    }
}

// ───────────────────────── generic fallback kernel ──────────────────────────
__global__ __launch_bounds__(256)
void nbrlist_generic(const float* __restrict__ pos,
                     const float* __restrict__ cell,
                     const float* __restrict__ cutoffs,
                     const int*   __restrict__ shifts,
                     const int*   __restrict__ ml_idx,
                     const int*   __restrict__ mm_idx,
                     float* __restrict__ out,
                     int n_ml, int n_mm, int S_img, long long P,
                     long long pairBlocks, int off_aligned)
{
    const long long P0 = (long long)n_ml * n_mm;
    float c[9];
    load_cell(cell, c);

    if (blockIdx.x >= (unsigned)pairBlocks) {
        offsets_fill(shifts, c, out, (long long)blockIdx.x - pairBlocks,
                     P, P0, off_aligned);
        return;
    }

    long long tid = (long long)blockIdx.x * blockDim.x + threadIdx.x;
    long long p0 = tid * 4;
    if (p0 >= P) return;

    const float cut0 = __ldg(cutoffs + 0), cut1 = __ldg(cutoffs + 1);
    const float c0sq = cut0 * cut0, c1sq = cut1 * cut1;

    for (int u = 0; u < 4; u++) {
        long long pp = p0 + u;
        if (pp >= P) break;
        int ss = (int)(pp / P0);
        long long kk = pp - (long long)ss * P0;
        int ii = (int)(kk / n_mm);
        int jj = (int)(kk - (long long)ii * n_mm);

        float svx, svy, svz;
        shift_vec(shifts, ss, c, svx, svy, svz);

        const int ia = __ldg(ml_idx + ii);
        const int ja = __ldg(mm_idx + jj);
        const float dx = __ldg(pos + 3 * ia + 0) - __ldg(pos + 3 * ja + 0) + svx;
        const float dy = __ldg(pos + 3 * ia + 1) - __ldg(pos + 3 * ja + 1) + svy;
        const float dz = __ldg(pos + 3 * ia + 2) - __ldg(pos + 3 * ja + 2) + svz;
        const float d2 = dx * dx + dy * dy + dz * dz;
        const float fi = (float)ia, fj = (float)ja;

        out[pp]         = fi;
        out[P + pp]     = fj;
        out[2 * P + pp] = fj;
        out[3 * P + pp] = fi;
        out[10 * P + pp]     = d2;
        out[10 * P + P + pp] = d2;
        const float m0 = d2 < c0sq ? 1.f : 0.f;
        const float m1 = d2 < c1sq ? 1.f : 0.f;
        out[12 * P + pp]         = m0;
        out[12 * P + P + pp]     = m0;
        out[12 * P + 2 * P + pp] = m1;
        out[12 * P + 3 * P + pp] = m1;
    }
}

extern "C" void kernel_launch(void* const* d_in, const int* in_sizes, int n_in,
                              void* d_out, int out_size)
{
    const float* pos     = (const float*)d_in[0];
    const float* cell    = (const float*)d_in[1];
    const float* cutoffs = (const float*)d_in[2];
    const int*   shifts  = (const int*)d_in[3];
    const int*   ml_idx  = (const int*)d_in[4];
    const int*   mm_idx  = (const int*)d_in[5];

    const int n_ml  = in_sizes[4];
    const int n_mm  = in_sizes[5];
    const int S     = in_sizes[3] / 3;
    const int S_img = S + 1;
    const long long P0 = (long long)n_ml * n_mm;
    const long long P  = (long long)S_img * P0;

    const int threads = 256;

    const long long tot4off   = (6 * P) / 4;
    const long long offBlocks = (tot4off + 4095) / 4096;
    const int off_aligned = (((3 * P0) % 16384) == 0) && (((3 * P) % 16384) == 0)
                            && ((P % 4) == 0) ? 1 : 0;

    // fast path gates: j-chunking; idx-fill block alignment (full blocks)
    const bool fast_ok = (n_mm % 1024 == 0)
                         && ((P0 % 16384) == 0) && ((P % 16384) == 0);

    if (fast_ok) {
        const int jchunks = n_mm / 1024;
        const long long pairBlocks = (long long)n_ml * jchunks;
        const long long idxBlocks  = (P + 4095) / 4096;   // P float4s in [0,4P)
        const long long totalBlocks = pairBlocks + idxBlocks + offBlocks;
        nbrlist_sloop<<<(unsigned)totalBlocks, threads>>>(
            pos, cell, cutoffs, shifts, ml_idx, mm_idx,
            (float*)d_out, n_ml, n_mm, S_img, P,
            pairBlocks, idxBlocks, jchunks, off_aligned);
    } else {
        const long long n_groups   = (P + 3) / 4;
        const long long pairBlocks = (n_groups + threads - 1) / threads;
        const long long totalBlocks = pairBlocks + offBlocks;
        nbrlist_generic<<<(unsigned)totalBlocks, threads>>>(
            pos, cell, cutoffs, shifts, ml_idx, mm_idx,
            (float*)d_out, n_ml, n_mm, S_img, P, pairBlocks, off_aligned);
    }
}

// round 12
// speedup vs baseline: 1.0319x; 1.0319x over previous
#include <cuda_runtime.h>
#include <cuda_bf16.h>
#include <cstdint>

// Inputs: 0 positions f32 (N)*3 | 1 cell f32 9 | 2 cutoffs f32 2
//         3 shifts i32 S*3 | 4 ml_idx i32 | 5 mm_idx i32
// Output (f32 flat): [0,2P) idx_i | [2P,4P) idx_j | [4P,10P) offsets(2P x 3)
//                    [10P,12P) d2_full | [12P,16P) masks(2 x 2P)
// P=(S+1)*n_ml*n_mm.  idx_i=[pi,pj], idx_j=[pj,pi], offsets=[-sv,+sv], d2=[d2,d2].
//
// R12 = R11 + pair blocks cover 2048 j's (two coalesced 1024-j groups per
// thread; second store at immediate +256 float4 offset). Streams get 2KB
// contiguous per image instead of 1KB; half the pair blocks.

__device__ __forceinline__ void load_cell(const float* __restrict__ cell,
                                          float c[9]) {
    #pragma unroll
    for (int u = 0; u < 9; u++) c[u] = __ldg(cell + u);
}

__device__ __forceinline__ void shift_vec(const int* __restrict__ shifts, int s,
                                          const float c[9],
                                          float& svx, float& svy, float& svz) {
    float sf0 = 0.f, sf1 = 0.f, sf2 = 0.f;
    if (s > 0) {
        sf0 = (float)__ldg(shifts + (s - 1) * 3 + 0);
        sf1 = (float)__ldg(shifts + (s - 1) * 3 + 1);
        sf2 = (float)__ldg(shifts + (s - 1) * 3 + 2);
    }
    svx = sf0 * c[0] + sf1 * c[3] + sf2 * c[6];
    svy = sf0 * c[1] + sf1 * c[4] + sf2 * c[7];
    svz = sf0 * c[2] + sf1 * c[5] + sf2 * c[8];
}

// offsets fill: 4096 consecutive float4s per block
__device__ __forceinline__ void offsets_fill(const int* __restrict__ shifts,
                                             const float c[9],
                                             float* __restrict__ out,
                                             long long fb, long long P,
                                             long long P0, int off_aligned)
{
    const long long tot4 = (6 * P) >> 2;
    const long long base4 = fb * 4096;
    if (base4 >= tot4) return;
    float4* dst = reinterpret_cast<float4*>(out + 4 * P);
    const long long halfF = 3 * P;

    if (off_aligned) {
        const long long fbase = base4 * 4;
        const bool negh = fbase < halfF;
        const long long fl = negh ? fbase : fbase - halfF;
        const int s = (int)(fl / (3 * P0));
        float svx, svy, svz;
        shift_vec(shifts, s, c, svx, svy, svz);
        const float X = negh ? -svx : svx;
        const float Y = negh ? -svy : svy;
        const float Z = negh ? -svz : svz;
        const float4 var[3] = { make_float4(X, Y, Z, X),
                                make_float4(Y, Z, X, Y),
                                make_float4(Z, X, Y, Z) };
        float4* p = dst + base4 + threadIdx.x;
        int v = (int)((base4 + threadIdx.x) % 3);
        const bool full = (base4 + 4096 <= tot4);
        if (full) {
            #pragma unroll
            for (int u = 0; u < 16; u++) {
                *p = var[v];
                p += 256;                       // +256 ≡ +1 (mod 3)
                v++; if (v == 3) v = 0;
            }
        } else {
            long long f4 = base4 + threadIdx.x;
            #pragma unroll
            for (int u = 0; u < 16; u++) {
                if (f4 < tot4) *p = var[v];
                p += 256; f4 += 256;
                v++; if (v == 3) v = 0;
            }
        }
    } else {
        for (int u = 0; u < 16; u++) {
            long long f4 = base4 + threadIdx.x + (long long)u * 256;
            if (f4 >= tot4) break;
            #pragma unroll
            for (int w = 0; w < 4; w++) {
                long long f = f4 * 4 + w;
                const bool negh = f < halfF;
                const long long fl = negh ? f : f - halfF;
                const long long row = fl / 3;
                const int comp = (int)(fl - row * 3);
                const int s = (int)(row / P0);
                float svx, svy, svz;
                shift_vec(shifts, s, c, svx, svy, svz);
                float val = (comp == 0) ? svx : (comp == 1) ? svy : svz;
                if (negh) val = -val;
                out[4 * P + f] = val;
            }
        }
    }
}

// idx fill: region [0,4P). Quarters: 0=pi, 1=pj, 2=pj, 3=pi.
__device__ __forceinline__ void idx_fill(const int* __restrict__ ml_idx,
                                         const int* __restrict__ mm_idx,
                                         float* __restrict__ out,
                                         long long fb, long long P,
                                         long long P0, int n_mm)
{
    const long long tot4 = P;
    const long long q4   = P >> 2;
    const long long base4 = fb * 4096;
    if (base4 >= tot4) return;

    const int q = (int)(base4 / q4);
    const long long rem4 = base4 - (long long)q * q4;
    const int local4 = (int)(rem4 % (P0 >> 2));
    int f = (local4 + (int)threadIdx.x) * 4;
    const bool is_pi = (q == 0 || q == 3);

    int i = f / n_mm;
    int j = f - i * n_mm;

    float4* p = reinterpret_cast<float4*>(out) + base4 + threadIdx.x;
    if (is_pi) {
        #pragma unroll
        for (int u = 0; u < 16; u++) {
            const float fi = (float)__ldg(ml_idx + i);
            *p = make_float4(fi, fi, fi, fi);
            p += 256;
            j += 1024;
            if (j >= n_mm) { j -= n_mm; i++; }
        }
    } else {
        #pragma unroll
        for (int u = 0; u < 16; u++) {
            const int4 jv = __ldg(reinterpret_cast<const int4*>(mm_idx + j));
            *p = make_float4((float)jv.x, (float)jv.y, (float)jv.z, (float)jv.w);
            p += 256;
            j += 1024;
            if (j >= n_mm) { j -= n_mm; i++; }
        }
    }
}

// load 4 consecutive j positions (group base jg must satisfy contig layout)
__device__ __forceinline__ void load_pj4(const float* __restrict__ pos,
                                         const int* __restrict__ mm_idx,
                                         int jg, float* px, float* py, float* pz,
                                         int4& jv)
{
    jv = __ldg(reinterpret_cast<const int4*>(mm_idx + jg));
    const bool contig = (jv.w == jv.x + 3) && (((3 * jv.x) & 3) == 0);
    if (contig) {
        const float4* pb = reinterpret_cast<const float4*>(pos + 3 * jv.x);
        const float4 v0 = __ldg(pb + 0);
        const float4 v1 = __ldg(pb + 1);
        const float4 v2 = __ldg(pb + 2);
        px[0] = v0.x; py[0] = v0.y; pz[0] = v0.z;
        px[1] = v0.w; py[1] = v1.x; pz[1] = v1.y;
        px[2] = v1.z; py[2] = v1.w; pz[2] = v2.x;
        px[3] = v2.y; py[3] = v2.z; pz[3] = v2.w;
    } else {
        const int jidx[4] = {jv.x, jv.y, jv.z, jv.w};
        #pragma unroll
        for (int u = 0; u < 4; u++) {
            px[u] = __ldg(pos + 3 * jidx[u] + 0);
            py[u] = __ldg(pos + 3 * jidx[u] + 1);
            pz[u] = __ldg(pos + 3 * jidx[u] + 2);
        }
    }
}

// ─────────── fast kernel: pair-compute (d2+masks) + both fills ───────────────
__global__ __launch_bounds__(256)
void nbrlist_sloop(const float* __restrict__ pos,
                   const float* __restrict__ cell,
                   const float* __restrict__ cutoffs,
                   const int*   __restrict__ shifts,
                   const int*   __restrict__ ml_idx,
                   const int*   __restrict__ mm_idx,
                   float* __restrict__ out,
                   int n_ml, int n_mm, int S_img, long long P,
                   long long pairBlocks, long long idxBlocks,
                   int jchunks, int off_aligned)
{
    const long long P0 = (long long)n_ml * n_mm;

    if (blockIdx.x >= (unsigned)(pairBlocks + idxBlocks)) {
        float c[9];
        load_cell(cell, c);
        offsets_fill(shifts, c, out,
                     (long long)blockIdx.x - pairBlocks - idxBlocks,
                     P, P0, off_aligned);
        return;
    }
    if (blockIdx.x >= (unsigned)pairBlocks) {
        idx_fill(ml_idx, mm_idx, out, (long long)blockIdx.x - pairBlocks,
                 P, P0, n_mm);
        return;
    }

    float c[9];
    load_cell(cell, c);

    const int bi = (int)blockIdx.x;
    const int i  = bi / jchunks;
    const int jc = bi - i * jchunks;
    const int j0 = jc * 2048 + (int)threadIdx.x * 4;   // group A
    const int j1 = j0 + 1024;                          // group B

    const float cut0 = __ldg(cutoffs + 0), cut1 = __ldg(cutoffs + 1);
    const float c0sq = cut0 * cut0, c1sq = cut1 * cut1;

    const int ia = __ldg(ml_idx + i);
    const float pix0 = __ldg(pos + 3 * ia + 0);
    const float piy0 = __ldg(pos + 3 * ia + 1);
    const float piz0 = __ldg(pos + 3 * ia + 2);

    float ax[4], ay[4], az[4], bx[4], by[4], bz[4];
    int4 jva, jvb;
    load_pj4(pos, mm_idx, j0, ax, ay, az, jva);
    load_pj4(pos, mm_idx, j1, bx, by, bz, jvb);

    const long long prow = (long long)i * n_mm + j0;
    const long long step4 = P0 >> 2;           // float4 stride per image

    float4* q_d2a = reinterpret_cast<float4*>(out + 10 * P + prow);
    float4* q_d2b = reinterpret_cast<float4*>(out + 11 * P + prow);
    float4* q_m0a = reinterpret_cast<float4*>(out + 12 * P + prow);
    float4* q_m0b = reinterpret_cast<float4*>(out + 13 * P + prow);
    float4* q_m1a = reinterpret_cast<float4*>(out + 14 * P + prow);
    float4* q_m1b = reinterpret_cast<float4*>(out + 15 * P + prow);

    for (int s = 0; s < S_img; s++) {
        float svx, svy, svz;
        shift_vec(shifts, s, c, svx, svy, svz);
        const float pix = pix0 + svx;
        const float piy = piy0 + svy;
        const float piz = piz0 + svz;

        // group A
        {
            float d2v[4];
            #pragma unroll
            for (int u = 0; u < 4; u++) {
                const float dx = pix - ax[u];
                const float dy = piy - ay[u];
                const float dz = piz - az[u];
                d2v[u] = dx * dx + dy * dy + dz * dz;
            }
            const float4 v_d2 = make_float4(d2v[0], d2v[1], d2v[2], d2v[3]);
            const float4 m0 = make_float4(d2v[0] < c0sq ? 1.f : 0.f,
                                          d2v[1] < c0sq ? 1.f : 0.f,
                                          d2v[2] < c0sq ? 1.f : 0.f,
                                          d2v[3] < c0sq ? 1.f : 0.f);
            const float4 m1 = make_float4(d2v[0] < c1sq ? 1.f : 0.f,
                                          d2v[1] < c1sq ? 1.f : 0.f,
                                          d2v[2] < c1sq ? 1.f : 0.f,
                                          d2v[3] < c1sq ? 1.f : 0.f);
            *q_d2a = v_d2;
            *q_d2b = v_d2;
            *q_m0a = m0;
            *q_m0b = m0;
            *q_m1a = m1;
            *q_m1b = m1;
        }
        // group B (immediate +256 float4 offset = +1024 floats)
        {
            float d2v[4];
            #pragma unroll
            for (int u = 0; u < 4; u++) {
                const float dx = pix - bx[u];
                const float dy = piy - by[u];
                const float dz = piz - bz[u];
                d2v[u] = dx * dx + dy * dy + dz * dz;
            }
            const float4 v_d2 = make_float4(d2v[0], d2v[1], d2v[2], d2v[3]);
            const float4 m0 = make_float4(d2v[0] < c0sq ? 1.f : 0.f,
                                          d2v[1] < c0sq ? 1.f : 0.f,
                                          d2v[2] < c0sq ? 1.f : 0.f,
                                          d2v[3] < c0sq ? 1.f : 0.f);
            const float4 m1 = make_float4(d2v[0] < c1sq ? 1.f : 0.f,
                                          d2v[1] < c1sq ? 1.f : 0.f,
                                          d2v[2] < c1sq ? 1.f : 0.f,
                                          d2v[3] < c1sq ? 1.f : 0.f);
            q_d2a[256] = v_d2;
            q_d2b[256] = v_d2;
            q_m0a[256] = m0;
            q_m0b[256] = m0;
            q_m1a[256] = m1;
            q_m1b[256] = m1;
        }
        q_d2a += step4; q_d2b += step4;
        q_m0a += step4; q_m0b += step4;
        q_m1a += step4; q_m1b += step4;
    }
}

// ───────────────────────── generic fallback kernel ──────────────────────────
__global__ __launch_bounds__(256)
void nbrlist_generic(const float* __restrict__ pos,
                     const float* __restrict__ cell,
                     const float* __restrict__ cutoffs,
                     const int*   __restrict__ shifts,
                     const int*   __restrict__ ml_idx,
                     const int*   __restrict__ mm_idx,
                     float* __restrict__ out,
                     int n_ml, int n_mm, int S_img, long long P,
                     long long pairBlocks, int off_aligned)
{
    const long long P0 = (long long)n_ml * n_mm;
    float c[9];
    load_cell(cell, c);

    if (blockIdx.x >= (unsigned)pairBlocks) {
        offsets_fill(shifts, c, out, (long long)blockIdx.x - pairBlocks,
                     P, P0, off_aligned);
        return;
    }

    long long tid = (long long)blockIdx.x * blockDim.x + threadIdx.x;
    long long p0 = tid * 4;
    if (p0 >= P) return;

    const float cut0 = __ldg(cutoffs + 0), cut1 = __ldg(cutoffs + 1);
    const float c0sq = cut0 * cut0, c1sq = cut1 * cut1;

    for (int u = 0; u < 4; u++) {
        long long pp = p0 + u;
        if (pp >= P) break;
        int ss = (int)(pp / P0);
        long long kk = pp - (long long)ss * P0;
        int ii = (int)(kk / n_mm);
        int jj = (int)(kk - (long long)ii * n_mm);

        float svx, svy, svz;
        shift_vec(shifts, ss, c, svx, svy, svz);

        const int ia = __ldg(ml_idx + ii);
        const int ja = __ldg(mm_idx + jj);
        const float dx = __ldg(pos + 3 * ia + 0) - __ldg(pos + 3 * ja + 0) + svx;
        const float dy = __ldg(pos + 3 * ia + 1) - __ldg(pos + 3 * ja + 1) + svy;
        const float dz = __ldg(pos + 3 * ia + 2) - __ldg(pos + 3 * ja + 2) + svz;
        const float d2 = dx * dx + dy * dy + dz * dz;
        const float fi = (float)ia, fj = (float)ja;

        out[pp]         = fi;
        out[P + pp]     = fj;
        out[2 * P + pp] = fj;
        out[3 * P + pp] = fi;
        out[10 * P + pp]     = d2;
        out[10 * P + P + pp] = d2;
        const float m0 = d2 < c0sq ? 1.f : 0.f;
        const float m1 = d2 < c1sq ? 1.f : 0.f;
        out[12 * P + pp]         = m0;
        out[12 * P + P + pp]     = m0;
        out[12 * P + 2 * P + pp] = m1;
        out[12 * P + 3 * P + pp] = m1;
    }
}

extern "C" void kernel_launch(void* const* d_in, const int* in_sizes, int n_in,
                              void* d_out, int out_size)
{
    const float* pos     = (const float*)d_in[0];
    const float* cell    = (const float*)d_in[1];
    const float* cutoffs = (const float*)d_in[2];
    const int*   shifts  = (const int*)d_in[3];
    const int*   ml_idx  = (const int*)d_in[4];
    const int*   mm_idx  = (const int*)d_in[5];

    const int n_ml  = in_sizes[4];
    const int n_mm  = in_sizes[5];
    const int S     = in_sizes[3] / 3;
    const int S_img = S + 1;
    const long long P0 = (long long)n_ml * n_mm;
    const long long P  = (long long)S_img * P0;

    const int threads = 256;

    const long long tot4off   = (6 * P) / 4;
    const long long offBlocks = (tot4off + 4095) / 4096;
    const int off_aligned = (((3 * P0) % 16384) == 0) && (((3 * P) % 16384) == 0)
                            && ((P % 4) == 0) ? 1 : 0;

    // fast path gates: 2048-j chunking; idx-fill block alignment (full blocks)
    const bool fast_ok = (n_mm % 2048 == 0)
                         && ((P0 % 16384) == 0) && ((P % 16384) == 0);

    if (fast_ok) {
        const int jchunks = n_mm / 2048;
        const long long pairBlocks = (long long)n_ml * jchunks;
        const long long idxBlocks  = (P + 4095) / 4096;
        const long long totalBlocks = pairBlocks + idxBlocks + offBlocks;
        nbrlist_sloop<<<(unsigned)totalBlocks, threads>>>(
            pos, cell, cutoffs, shifts, ml_idx, mm_idx,
            (float*)d_out, n_ml, n_mm, S_img, P,
            pairBlocks, idxBlocks, jchunks, off_aligned);
    } else {
        const long long n_groups   = (P + 3) / 4;
        const long long pairBlocks = (n_groups + threads - 1) / threads;
        const long long totalBlocks = pairBlocks + offBlocks;
        nbrlist_generic<<<(unsigned)totalBlocks, threads>>>(
            pos, cell, cutoffs, shifts, ml_idx, mm_idx,
            (float*)d_out, n_ml, n_mm, S_img, P, pairBlocks, off_aligned);
    }
}